// round 15
// baseline (speedup 1.0000x reference)
#include <cuda_runtime.h>
#include <cuda_bf16.h>
#include <math.h>
#include <stdint.h>

#define D    65536
#define Q    32
#define E    300
#define KP   320          // padded k (input channels)
#define NP2  320          // padded n (output channels)
#define SROW 40           // smem row pitch (bf16) for sim kernel (k-chunk 32)
#define SRW2 72           // smem row pitch (bf16) for conv kernel (k-chunk 64)
#define NSIMB 512         // sim CTA chunks per type (D/128)

// ---------------- device scratch (static, allowed) ----------------
__device__ __nv_bfloat16 g_Wb[3 * NP2 * KP];               // bf16 weights [j][e][i], zero-padded
__device__ __nv_bfloat16 g_dembh[(size_t)(D + 16) * KP];   // bf16 doc embeds (pads stay zero)
__device__ __nv_bfloat16 g_dconvh[(size_t)(D + 16) * KP];  // bf16 doc conv+residual (pads zero)
__device__ __nv_bfloat16 g_qnh[2 * Q * KP];                // bf16 normalized q vecs (emb, conv)
__device__ float g_ohT[(size_t)Q * D];                     // transposed doc1_sim [q][d]
__device__ float g_part0[Q][32][5];                        // one-hot top5 partials (32 chunks)
__device__ float g_part2[2][Q][NSIMB][5];                  // sim top5 partials (512 CTA chunks)

// ---------------- PTX helpers ----------------
__device__ __forceinline__ uint32_t smem_u32(const void* p) {
    uint32_t a;
    asm("{ .reg .u64 t; cvta.to.shared.u64 t, %1; cvt.u32.u64 %0, t; }" : "=r"(a) : "l"(p));
    return a;
}
__device__ __forceinline__ void cpasync16(uint32_t s, const void* g) {
    asm volatile("cp.async.cg.shared.global [%0], [%1], 16;" :: "r"(s), "l"(g));
}
__device__ __forceinline__ void cpasync_commit() {
    asm volatile("cp.async.commit_group;" ::: "memory");
}
template <int N>
__device__ __forceinline__ void cpasync_wait() {
    asm volatile("cp.async.wait_group %0;" :: "n"(N) : "memory");
}
__device__ __forceinline__ void mma16816(float* c, const uint32_t* a, uint32_t b0, uint32_t b1) {
    asm volatile(
        "mma.sync.aligned.m16n8k16.row.col.f32.bf16.bf16.f32 "
        "{%0,%1,%2,%3}, {%4,%5,%6,%7}, {%8,%9}, {%0,%1,%2,%3};"
        : "+f"(c[0]), "+f"(c[1]), "+f"(c[2]), "+f"(c[3])
        : "r"(a[0]), "r"(a[1]), "r"(a[2]), "r"(a[3]), "r"(b0), "r"(b1));
}
__device__ __forceinline__ void ldsm_x4(uint32_t* r, uint32_t addr) {
    asm volatile("ldmatrix.sync.aligned.m8n8.x4.shared.b16 {%0,%1,%2,%3}, [%4];"
                 : "=r"(r[0]), "=r"(r[1]), "=r"(r[2]), "=r"(r[3]) : "r"(addr));
}
__device__ __forceinline__ float fast_sigmoid(float x) {
    return 1.f / (1.f + __expf(-x));
}

// ---------------- top-5 helpers ----------------
__device__ __forceinline__ void ins5(float* a, float v) {
    if (v <= a[4]) return;
    a[4] = v;
#pragma unroll
    for (int i = 4; i > 0; i--) {
        if (a[i] > a[i - 1]) { float t = a[i - 1]; a[i - 1] = a[i]; a[i] = t; }
        else break;
    }
}
__device__ __forceinline__ void merge5_xor(float* t5, int off) {
    float o[5];
#pragma unroll
    for (int i = 0; i < 5; i++) o[i] = __shfl_xor_sync(0xffffffffu, t5[i], off);
#pragma unroll
    for (int i = 0; i < 5; i++) ins5(t5, o[i]);
}

// ---------------- K0: bf16 GEMM weights [j][e][i], padded ----------------
__global__ void wb_kernel(const float* __restrict__ conv_w) {
    int idx = blockIdx.x * 256 + threadIdx.x;
    if (idx >= 3 * NP2 * KP) return;
    int i = idx % KP;
    int rem = idx / KP;
    int e = rem % NP2;
    int j = rem / NP2;
    float v = (i < 300 && e < 300) ? conv_w[e * 900 + i * 3 + j] : 0.f;
    g_Wb[idx] = __float2bfloat16(v);
}

// ---------------- K1: doc gather -> bf16 padded (warp per row, vectorized) ----------------
__global__ void gather_kernel(const int* __restrict__ doc1, const float* __restrict__ embeds) {
    int row = blockIdx.x * 8 + (threadIdx.x >> 5);
    int lane = threadIdx.x & 31;
    if (row >= D) return;
    const float4* src = (const float4*)(embeds + (size_t)doc1[row] * 300);
    __nv_bfloat16* dst = g_dembh + (size_t)row * KP;
    for (int i = lane; i < 75; i += 32) {
        float4 v = src[i];
        __nv_bfloat162 lo = __floats2bfloat162_rn(v.x, v.y);
        __nv_bfloat162 hi = __floats2bfloat162_rn(v.z, v.w);
        uint2 pk;
        pk.x = *(uint32_t*)&lo;
        pk.y = *(uint32_t*)&hi;
        *(uint2*)(dst + i * 4) = pk;
    }
}

// ---------------- K2: query conv + normalize -> bf16 (parallel) ----------------
__global__ void __launch_bounds__(384) conv_q_kernel(const int* __restrict__ question,
                                                     const float* __restrict__ embeds,
                                                     const float* __restrict__ conv_w,
                                                     const float* __restrict__ conv_b) {
    __shared__ float xs4[4][300];
    __shared__ float qc[300];
    __shared__ float red[2];
    int t = blockIdx.x;
    int tid = threadIdx.x;
    int wid = tid >> 5, lane = tid & 31;

    for (int idx = tid; idx < 1200; idx += 384) {
        int j = idx / 300, i = idx - j * 300;
        int tt = t + j;
        xs4[j][i] = (tt < Q) ? embeds[(size_t)question[tt] * 300 + i] : 0.f;
    }
    __syncthreads();

    for (int e = wid; e < 300; e += 12) {
        const float* w = conv_w + e * 900;
        float acc = 0.f;
        for (int kk = lane; kk < 900; kk += 32) {
            int i = kk / 3, j = kk - 3 * i;
            acc = fmaf(w[kk], xs4[1 + j][i], acc);
        }
#pragma unroll
        for (int o = 16; o; o >>= 1) acc += __shfl_down_sync(0xffffffffu, acc, o);
        if (lane == 0)
            qc[e] = fast_sigmoid(acc + conv_b[e]) + xs4[0][e];
    }
    __syncthreads();
    if (wid == 0) {
        float se = 0.f, sc = 0.f;
        for (int i = lane; i < 300; i += 32) {
            float a = xs4[0][i]; se += a * a;
            float c = qc[i];     sc += c * c;
        }
#pragma unroll
        for (int o = 16; o; o >>= 1) {
            se += __shfl_xor_sync(0xffffffffu, se, o);
            sc += __shfl_xor_sync(0xffffffffu, sc, o);
        }
        if (lane == 0) { red[0] = rsqrtf(se); red[1] = rsqrtf(sc); }
    }
    __syncthreads();
    if (tid < 300) {
        g_qnh[0 * Q * KP + t * KP + tid] = __float2bfloat16(xs4[0][tid] * red[0]);
        g_qnh[1 * Q * KP + t * KP + tid] = __float2bfloat16(qc[tid] * red[1]);
    }
}

// ---------------- K3: transpose doc1_sim [D][Q] -> g_ohT [Q][D] ----------------
__global__ void __launch_bounds__(256) transpose_kernel(const float* __restrict__ doc1_sim) {
    __shared__ float tbuf[32][33];
    int d0 = blockIdx.x * 32;
    int tx = threadIdx.x & 31, ty = threadIdx.x >> 5;
    for (int r = ty; r < 32; r += 8)
        tbuf[r][tx] = doc1_sim[(size_t)(d0 + r) * 32 + tx];
    __syncthreads();
    for (int r = ty; r < 32; r += 8)
        g_ohT[(size_t)r * D + d0 + tx] = tbuf[tx][r];
}

// ---------------- K4: doc conv as HMMA bf16 GEMM (2-buffer/1-sync, k-chunk 64) ----------------
// grid (5, 512): x = 64-channel tile, y = 128-doc tile. 256 threads (8 warps, 4m x 2n, warp 32x32).
#define A_STG2 (128 * SRW2 * 2)   // 18432 B per A stage
#define B_STG2 (64 * SRW2 * 2)    // 9216 B per B stage
#define CONV_SMEM (2 * (A_STG2 + B_STG2))
__global__ void __launch_bounds__(256, 3) conv_gemm_kernel(const float* __restrict__ conv_b) {
    extern __shared__ __nv_bfloat16 dyn_smem[];
    __nv_bfloat16* As = dyn_smem;                         // [2][128][SRW2]
    __nv_bfloat16* Bs = dyn_smem + 2 * 128 * SRW2;        // [2][64][SRW2]

    int tid = threadIdx.x;
    int wid = tid >> 5, lane = tid & 31;
    int wm = wid >> 1, wn = wid & 1;
    int g = lane >> 2, tg = lane & 3;

    int n0g  = blockIdx.x * 64;
    int pos0 = blockIdx.y * 128;

    uint32_t As0 = smem_u32(As);
    uint32_t Bs0 = smem_u32(Bs);
    uint32_t a_off = ((wm * 32 + (lane & 15)) * SRW2 + ((lane >> 4) << 3)) * 2;
    uint32_t b_off = (((wn * 32) + (lane & 7) + ((lane >> 4) << 3)) * SRW2 + (((lane >> 3) & 1) << 3)) * 2;

    float acc[2][4][4];
#pragma unroll
    for (int mt = 0; mt < 2; mt++)
#pragma unroll
        for (int nt = 0; nt < 4; nt++)
#pragma unroll
            for (int i = 0; i < 4; i++) acc[mt][nt][i] = 0.f;

    auto load_stage = [&](int s, int c) {
        int j = c / 5;
        int k0 = (c - j * 5) * 64;
        const __nv_bfloat16* Ag = g_dembh + (size_t)(pos0 + 1 + j) * KP + k0;
        const __nv_bfloat16* Bg = g_Wb + ((size_t)j * NP2 + n0g) * KP + k0;
        uint32_t a_s = As0 + s * A_STG2;
        uint32_t b_s = Bs0 + s * B_STG2;
#pragma unroll
        for (int u = 0; u < 4; u++) {
            int v = tid + u * 256;
            int r = v >> 3, cc = v & 7;
            cpasync16(a_s + (r * SRW2 + cc * 8) * 2, Ag + (size_t)r * KP + cc * 8);
        }
#pragma unroll
        for (int u = 0; u < 2; u++) {
            int v = tid + u * 256;
            int r = v >> 3, cc = v & 7;
            cpasync16(b_s + (r * SRW2 + cc * 8) * 2, Bg + (size_t)r * KP + cc * 8);
        }
        cpasync_commit();
    };

    load_stage(0, 0);

    for (int c = 0; c < 15; c++) {
        int s = c & 1;
        cpasync_wait<0>();
        __syncthreads();
        if (c + 1 < 15) load_stage(s ^ 1, c + 1);

        uint32_t a_base = As0 + s * A_STG2 + a_off;
        uint32_t b_base = Bs0 + s * B_STG2 + b_off;
#pragma unroll
        for (int ks = 0; ks < 4; ks++) {
            uint32_t a[2][4], b[2][4];
            ldsm_x4(a[0], a_base + ks * 32);
            ldsm_x4(a[1], a_base + ks * 32 + 16 * SRW2 * 2);
            ldsm_x4(b[0], b_base + ks * 32);
            ldsm_x4(b[1], b_base + ks * 32 + 16 * SRW2 * 2);
#pragma unroll
            for (int p = 0; p < 2; p++) {
#pragma unroll
                for (int mt = 0; mt < 2; mt++) {
                    mma16816(acc[mt][2 * p + 0], a[mt], b[p][0], b[p][1]);
                    mma16816(acc[mt][2 * p + 1], a[mt], b[p][2], b[p][3]);
                }
            }
        }
    }

#pragma unroll
    for (int mt = 0; mt < 2; mt++) {
#pragma unroll
        for (int nt = 0; nt < 4; nt++) {
            int ch = n0g + wn * 32 + nt * 8 + tg * 2;
            if (ch >= 300) continue;
            float bia0 = __ldg(conv_b + ch);
            float bia1 = __ldg(conv_b + ch + 1);
#pragma unroll
            for (int h = 0; h < 2; h++) {
                int row = pos0 + wm * 32 + mt * 16 + g + h * 8;
                size_t gi = (size_t)row * KP + ch;
                float2 res = __bfloat1622float2(*(const __nv_bfloat162*)&g_dembh[gi]);
                float o0 = fast_sigmoid(acc[mt][nt][h * 2 + 0] + bia0) + res.x;
                float o1 = fast_sigmoid(acc[mt][nt][h * 2 + 1] + bia1) + res.y;
                *(__nv_bfloat162*)&g_dconvh[gi] = __floats2bfloat162_rn(o0, o1);
            }
        }
    }
}

// ---------------- K5: cosine sims as HMMA GEMM + fused top-5 partials ----------------
// grid (D/128, 2 types), 256 threads, 8 warps (warp = 16 d rows). Never materializes S.
#define A_STAGE_SB (128 * SROW * 2)
#define BS_STAGE_B (32 * SROW * 2)
__global__ void __launch_bounds__(256) sim_gemm_kernel() {
    __shared__ __nv_bfloat16 As[3][128][SROW];
    __shared__ __nv_bfloat16 Bs[3][32][SROW];
    __shared__ float sm_top[8][Q][5];     // per-warp top5 per q

    int tid = threadIdx.x;
    int wid = tid >> 5, lane = tid & 31;
    int g = lane >> 2, tg = lane & 3;
    int type = blockIdx.y;
    int pos0 = blockIdx.x * 128;

    const __nv_bfloat16* Asrc = type ? g_dconvh : g_dembh;
    const __nv_bfloat16* Bsrc = g_qnh + (size_t)type * Q * KP;

    uint32_t As0 = smem_u32(&As[0][0][0]);
    uint32_t Bs0 = smem_u32(&Bs[0][0][0]);
    uint32_t a_off = ((wid * 16 + (lane & 15)) * SROW + ((lane >> 4) << 3)) * 2;
    uint32_t b_off = (((lane & 7) + ((lane >> 4) << 3)) * SROW + (((lane >> 3) & 1) << 3)) * 2;

    float acc[4][4];
#pragma unroll
    for (int nt = 0; nt < 4; nt++)
#pragma unroll
        for (int i = 0; i < 4; i++) acc[nt][i] = 0.f;
    float ssq0 = 0.f, ssq1 = 0.f;

    auto load_stage = [&](int s, int kc) {
        int k0 = kc * 32;
        const __nv_bfloat16* Ag = Asrc + (size_t)pos0 * KP + k0;
#pragma unroll
        for (int u = 0; u < 2; u++) {
            int v = tid + u * 256;
            int r = v >> 2, cc = v & 3;
            cpasync16(smem_u32(&As[s][r][cc * 8]), Ag + (size_t)r * KP + cc * 8);
        }
        if (tid < 128) {
            int r = tid >> 2, cc = tid & 3;
            cpasync16(smem_u32(&Bs[s][r][cc * 8]), Bsrc + (size_t)r * KP + k0 + cc * 8);
        }
        cpasync_commit();
    };

    load_stage(0, 0);
    load_stage(1, 1);

    for (int kc = 0; kc < 10; kc++) {
        int s = kc % 3;
        if (kc < 9) cpasync_wait<1>();
        else        cpasync_wait<0>();
        __syncthreads();

        uint32_t a_base = As0 + s * A_STAGE_SB + a_off;
        uint32_t b_base = Bs0 + s * BS_STAGE_B + b_off;
#pragma unroll
        for (int ks = 0; ks < 2; ks++) {
            uint32_t a[4], b[2][4];
            ldsm_x4(a, a_base + ks * 32);
            ldsm_x4(b[0], b_base + ks * 32);
            ldsm_x4(b[1], b_base + ks * 32 + 16 * SROW * 2);
            float2 f0 = __bfloat1622float2(*(const __nv_bfloat162*)&a[0]);
            float2 f1 = __bfloat1622float2(*(const __nv_bfloat162*)&a[1]);
            float2 f2 = __bfloat1622float2(*(const __nv_bfloat162*)&a[2]);
            float2 f3 = __bfloat1622float2(*(const __nv_bfloat162*)&a[3]);
            ssq0 = fmaf(f0.x, f0.x, fmaf(f0.y, f0.y, fmaf(f2.x, f2.x, fmaf(f2.y, f2.y, ssq0))));
            ssq1 = fmaf(f1.x, f1.x, fmaf(f1.y, f1.y, fmaf(f3.x, f3.x, fmaf(f3.y, f3.y, ssq1))));
#pragma unroll
            for (int p = 0; p < 2; p++) {
                mma16816(acc[2 * p + 0], a, b[p][0], b[p][1]);
                mma16816(acc[2 * p + 1], a, b[p][2], b[p][3]);
            }
        }
        if (kc + 2 < 10) load_stage((kc + 2) % 3, kc + 2);
    }

    ssq0 += __shfl_xor_sync(0xffffffffu, ssq0, 1);
    ssq0 += __shfl_xor_sync(0xffffffffu, ssq0, 2);
    ssq1 += __shfl_xor_sync(0xffffffffu, ssq1, 1);
    ssq1 += __shfl_xor_sync(0xffffffffu, ssq1, 2);
    float dinv0 = rsqrtf(ssq0);
    float dinv1 = rsqrtf(ssq1);

    // fused top-5: per (nt, parity) -> q = nt*8 + tg*2 + p; values at d0, d0+8.
    // merge across g (xor 4,8,16; tg invariant) -> warp-level top5 of its 16 docs.
#pragma unroll
    for (int nt = 0; nt < 4; nt++) {
#pragma unroll
        for (int p = 0; p < 2; p++) {
            float t5[5] = {-1e30f, -1e30f, -1e30f, -1e30f, -1e30f};
            float v0 = (p == 0 ? acc[nt][0] : acc[nt][1]) * dinv0;
            float v1 = (p == 0 ? acc[nt][2] : acc[nt][3]) * dinv1;
            ins5(t5, v0);
            ins5(t5, v1);
            merge5_xor(t5, 4); merge5_xor(t5, 8); merge5_xor(t5, 16);
            if (g == 0) {
                int q = nt * 8 + tg * 2 + p;
#pragma unroll
                for (int i = 0; i < 5; i++) sm_top[wid][q][i] = t5[i];
            }
        }
    }
    __syncthreads();

    // warp 0: merge 8 warps' top5 per q -> CTA partial
    if (wid == 0) {
        int q = lane;
        float t5[5] = {-1e30f, -1e30f, -1e30f, -1e30f, -1e30f};
#pragma unroll
        for (int w = 0; w < 8; w++)
#pragma unroll
            for (int i = 0; i < 5; i++) ins5(t5, sm_top[w][q][i]);
#pragma unroll
        for (int i = 0; i < 5; i++) g_part2[type][q][blockIdx.x][i] = t5[i];
    }
}

// ---------------- K6: one-hot top-5 stage 1 (32 chunks) ----------------
__global__ void __launch_bounds__(256) topk1_kernel() {
    int chunk = blockIdx.x;
    int wid = threadIdx.x >> 5, lane = threadIdx.x & 31;
    for (int qq = 0; qq < 4; qq++) {
        int q = wid * 4 + qq;
        const float4* base = (const float4*)(g_ohT + (size_t)q * D + chunk * 2048);
        float t5[5] = {-1e30f, -1e30f, -1e30f, -1e30f, -1e30f};
#pragma unroll 4
        for (int it = 0; it < 16; it++) {
            float4 v = __ldg(base + it * 32 + lane);
            ins5(t5, v.x); ins5(t5, v.y); ins5(t5, v.z); ins5(t5, v.w);
        }
        merge5_xor(t5, 16); merge5_xor(t5, 8); merge5_xor(t5, 4);
        merge5_xor(t5, 2);  merge5_xor(t5, 1);
        if (lane == 0) {
#pragma unroll
            for (int i = 0; i < 5; i++) g_part0[q][chunk][i] = t5[i];
        }
    }
}

// ---------------- K7: fused stage-2 merges + MLP + emit + loss (one block) ----------------
__global__ void __launch_bounds__(1024) tail_kernel(
        const float* __restrict__ W1, const float* __restrict__ b1,
        const float* __restrict__ W2, const float* __restrict__ b2,
        const float* __restrict__ a1, const float* __restrict__ target,
        float* __restrict__ out, int out_size) {
    __shared__ float feats[Q * 6];
    int wid = threadIdx.x >> 5, lane = threadIdx.x & 31;

    // 96 (type,q) tasks over 32 warps
    for (int t = wid; t < 96; t += 32) {
        float t5[5] = {-1e30f, -1e30f, -1e30f, -1e30f, -1e30f};
        int type, q;
        if (t < 32) {              // one-hot: 32 chunks
            type = 0; q = t;
            const float* p = g_part0[q][lane];
#pragma unroll
            for (int i = 0; i < 5; i++) ins5(t5, p[i]);
        } else {                   // sim types: 512 chunks
            type = 1 + (t - 32) / 32;
            q = (t - 32) & 31;
            const float (*p2)[5] = g_part2[type - 1][q];
            for (int c = lane; c < NSIMB; c += 32)
#pragma unroll
                for (int i = 0; i < 5; i++) ins5(t5, p2[c][i]);
        }
        merge5_xor(t5, 16); merge5_xor(t5, 8); merge5_xor(t5, 4);
        merge5_xor(t5, 2);  merge5_xor(t5, 1);
        if (lane == 0) {
            float m = (t5[0] + t5[1] + t5[2] + t5[3] + t5[4]) * 0.2f;
            feats[q * 6 + type * 2 + 0] = t5[0];
            feats[q * 6 + type * 2 + 1] = m;
        }
    }
    __syncthreads();

    if (wid == 0) {
        int q = lane;
        float f[6];
#pragma unroll
        for (int j = 0; j < 6; j++) f[j] = feats[q * 6 + j];
        float a = a1[0];
        float logit = b2[0];
#pragma unroll
        for (int i = 0; i < 8; i++) {
            float h = b1[i];
#pragma unroll
            for (int j = 0; j < 6; j++) h = fmaf(f[j], W1[i * 6 + j], h);
            h = h > 0.f ? h : a * h;
            logit = fmaf(h, W2[i], logit);
        }
        float s = 1.f / (1.f + expf(-logit));
#pragma unroll
        for (int o = 16; o; o >>= 1) s += __shfl_xor_sync(0xffffffffu, s, o);
        if (q == 0) {
            float emit = s / 32.f;
            float t = target[0];
            float sp = log1pf(expf(-fabsf(emit))) + fmaxf(emit, 0.f);
            float loss = sp - t * emit;
            out[0] = loss;
            if (out_size > 1) out[1] = emit;
        }
    }
}

// ---------------- launch ----------------
extern "C" void kernel_launch(void* const* d_in, const int* in_sizes, int n_in,
                              void* d_out, int out_size) {
    const int*   doc1     = (const int*)d_in[0];
    const int*   question = (const int*)d_in[1];
    const float* doc1_sim = (const float*)d_in[2];
    const float* target   = (const float*)d_in[3];
    const float* embeds   = (const float*)d_in[4];
    const float* conv_w   = (const float*)d_in[5];
    const float* conv_b   = (const float*)d_in[6];
    const float* W1       = (const float*)d_in[7];
    const float* b1       = (const float*)d_in[8];
    const float* W2       = (const float*)d_in[9];
    const float* b2       = (const float*)d_in[10];
    const float* a1       = (const float*)d_in[11];
    float* out = (float*)d_out;

    cudaFuncSetAttribute(conv_gemm_kernel,
                         cudaFuncAttributeMaxDynamicSharedMemorySize, CONV_SMEM);

    wb_kernel<<<(3 * NP2 * KP + 255) / 256, 256>>>(conv_w);             // 1
    conv_q_kernel<<<Q, 384>>>(question, embeds, conv_w, conv_b);         // 2
    gather_kernel<<<D / 8, 256>>>(doc1, embeds);                         // 3
    {
        dim3 grid(5, D / 128);
        conv_gemm_kernel<<<grid, 256, CONV_SMEM>>>(conv_b);              // 4: ncu capture target
    }
    transpose_kernel<<<D / 32, 256>>>(doc1_sim);                         // 5
    {
        dim3 grid(D / 128, 2);
        sim_gemm_kernel<<<grid, 256>>>();                                // 6
    }
    topk1_kernel<<<32, 256>>>();                                         // 7
    tail_kernel<<<1, 1024>>>(W1, b1, W2, b2, a1, target, out, out_size); // 8
}

// round 16
// speedup vs baseline: 1.1570x; 1.1570x over previous
#include <cuda_runtime.h>
#include <cuda_bf16.h>
#include <math.h>
#include <stdint.h>

#define D    65536
#define Q    32
#define E    300
#define KP   320          // padded k (input channels)
#define NP2  320          // padded n (output channels)
#define SROW 40           // smem row pitch (bf16) for sim kernel (k-chunk 32)
#define SRW2 72           // smem row pitch (bf16) for conv kernel (k-chunk 64)

// ---------------- device scratch (static, allowed) ----------------
__device__ __nv_bfloat16 g_Wb[3 * NP2 * KP];               // bf16 weights [j][e][i], zero-padded
__device__ __nv_bfloat16 g_dembh[(size_t)(D + 16) * KP];   // bf16 doc embeds (pads stay zero)
__device__ __nv_bfloat16 g_dconvh[(size_t)(D + 16) * KP];  // bf16 doc conv+residual (pads zero)
__device__ __nv_bfloat16 g_qnh[2 * Q * KP];                // bf16 normalized q vecs (emb, conv)
__device__ float g_ohT[(size_t)Q * D];                     // transposed doc1_sim [q][d]
__device__ float g_S[2][(size_t)Q * D];                    // sims [q][d]: 0 emb, 1 conv
__device__ float g_part[3][Q][32][5];                      // stage-1 top5 partials
__device__ float g_feats[Q * 6];

// ---------------- PTX helpers ----------------
__device__ __forceinline__ uint32_t smem_u32(const void* p) {
    uint32_t a;
    asm("{ .reg .u64 t; cvta.to.shared.u64 t, %1; cvt.u32.u64 %0, t; }" : "=r"(a) : "l"(p));
    return a;
}
__device__ __forceinline__ void cpasync16(uint32_t s, const void* g) {
    asm volatile("cp.async.cg.shared.global [%0], [%1], 16;" :: "r"(s), "l"(g));
}
__device__ __forceinline__ void cpasync_commit() {
    asm volatile("cp.async.commit_group;" ::: "memory");
}
template <int N>
__device__ __forceinline__ void cpasync_wait() {
    asm volatile("cp.async.wait_group %0;" :: "n"(N) : "memory");
}
__device__ __forceinline__ void mma16816(float* c, const uint32_t* a, uint32_t b0, uint32_t b1) {
    asm volatile(
        "mma.sync.aligned.m16n8k16.row.col.f32.bf16.bf16.f32 "
        "{%0,%1,%2,%3}, {%4,%5,%6,%7}, {%8,%9}, {%0,%1,%2,%3};"
        : "+f"(c[0]), "+f"(c[1]), "+f"(c[2]), "+f"(c[3])
        : "r"(a[0]), "r"(a[1]), "r"(a[2]), "r"(a[3]), "r"(b0), "r"(b1));
}
__device__ __forceinline__ void ldsm_x4(uint32_t* r, uint32_t addr) {
    asm volatile("ldmatrix.sync.aligned.m8n8.x4.shared.b16 {%0,%1,%2,%3}, [%4];"
                 : "=r"(r[0]), "=r"(r[1]), "=r"(r[2]), "=r"(r[3]) : "r"(addr));
}
__device__ __forceinline__ float fast_sigmoid(float x) {
    return 1.f / (1.f + __expf(-x));
}

// ---------------- K0: bf16 GEMM weights [j][e][i], padded ----------------
__global__ void wb_kernel(const float* __restrict__ conv_w) {
    int idx = blockIdx.x * 256 + threadIdx.x;
    if (idx >= 3 * NP2 * KP) return;
    int i = idx % KP;
    int rem = idx / KP;
    int e = rem % NP2;
    int j = rem / NP2;
    float v = (i < 300 && e < 300) ? conv_w[e * 900 + i * 3 + j] : 0.f;
    g_Wb[idx] = __float2bfloat16(v);
}

// ---------------- K1: doc gather -> bf16 padded (warp per row, vectorized) ----------------
__global__ void gather_kernel(const int* __restrict__ doc1, const float* __restrict__ embeds) {
    int row = blockIdx.x * 8 + (threadIdx.x >> 5);
    int lane = threadIdx.x & 31;
    if (row >= D) return;
    const float4* src = (const float4*)(embeds + (size_t)doc1[row] * 300);
    __nv_bfloat16* dst = g_dembh + (size_t)row * KP;
    for (int i = lane; i < 75; i += 32) {
        float4 v = src[i];
        __nv_bfloat162 lo = __floats2bfloat162_rn(v.x, v.y);
        __nv_bfloat162 hi = __floats2bfloat162_rn(v.z, v.w);
        uint2 pk;
        pk.x = *(uint32_t*)&lo;
        pk.y = *(uint32_t*)&hi;
        *(uint2*)(dst + i * 4) = pk;
    }
}

// ---------------- K2: query conv + normalize -> bf16 (parallel) ----------------
__global__ void __launch_bounds__(384) conv_q_kernel(const int* __restrict__ question,
                                                     const float* __restrict__ embeds,
                                                     const float* __restrict__ conv_w,
                                                     const float* __restrict__ conv_b) {
    __shared__ float xs4[4][300];
    __shared__ float qc[300];
    __shared__ float red[2];
    int t = blockIdx.x;
    int tid = threadIdx.x;
    int wid = tid >> 5, lane = tid & 31;

    for (int idx = tid; idx < 1200; idx += 384) {
        int j = idx / 300, i = idx - j * 300;
        int tt = t + j;
        xs4[j][i] = (tt < Q) ? embeds[(size_t)question[tt] * 300 + i] : 0.f;
    }
    __syncthreads();

    for (int e = wid; e < 300; e += 12) {
        const float* w = conv_w + e * 900;
        float acc = 0.f;
        for (int kk = lane; kk < 900; kk += 32) {
            int i = kk / 3, j = kk - 3 * i;
            acc = fmaf(w[kk], xs4[1 + j][i], acc);
        }
#pragma unroll
        for (int o = 16; o; o >>= 1) acc += __shfl_down_sync(0xffffffffu, acc, o);
        if (lane == 0)
            qc[e] = fast_sigmoid(acc + conv_b[e]) + xs4[0][e];
    }
    __syncthreads();
    if (wid == 0) {
        float se = 0.f, sc = 0.f;
        for (int i = lane; i < 300; i += 32) {
            float a = xs4[0][i]; se += a * a;
            float c = qc[i];     sc += c * c;
        }
#pragma unroll
        for (int o = 16; o; o >>= 1) {
            se += __shfl_xor_sync(0xffffffffu, se, o);
            sc += __shfl_xor_sync(0xffffffffu, sc, o);
        }
        if (lane == 0) { red[0] = rsqrtf(se); red[1] = rsqrtf(sc); }
    }
    __syncthreads();
    if (tid < 300) {
        g_qnh[0 * Q * KP + t * KP + tid] = __float2bfloat16(xs4[0][tid] * red[0]);
        g_qnh[1 * Q * KP + t * KP + tid] = __float2bfloat16(qc[tid] * red[1]);
    }
}

// ---------------- K3: transpose doc1_sim [D][Q] -> g_ohT [Q][D] ----------------
__global__ void __launch_bounds__(256) transpose_kernel(const float* __restrict__ doc1_sim) {
    __shared__ float tbuf[32][33];
    int d0 = blockIdx.x * 32;
    int tx = threadIdx.x & 31, ty = threadIdx.x >> 5;
    for (int r = ty; r < 32; r += 8)
        tbuf[r][tx] = doc1_sim[(size_t)(d0 + r) * 32 + tx];
    __syncthreads();
    for (int r = ty; r < 32; r += 8)
        g_ohT[(size_t)r * D + d0 + tx] = tbuf[tx][r];
}

// ---------------- K4: doc conv as HMMA bf16 GEMM (2-buffer/1-sync, k-chunk 64) ----------------
// grid (5, 512): x = 64-channel tile, y = 128-doc tile. 256 threads (8 warps, 4m x 2n, warp 32x32).
#define A_STG2 (128 * SRW2 * 2)   // 18432 B per A stage
#define B_STG2 (64 * SRW2 * 2)    // 9216 B per B stage
#define CONV_SMEM (2 * (A_STG2 + B_STG2))
__global__ void __launch_bounds__(256, 3) conv_gemm_kernel(const float* __restrict__ conv_b) {
    extern __shared__ __nv_bfloat16 dyn_smem[];
    __nv_bfloat16* As = dyn_smem;                         // [2][128][SRW2]
    __nv_bfloat16* Bs = dyn_smem + 2 * 128 * SRW2;        // [2][64][SRW2]

    int tid = threadIdx.x;
    int wid = tid >> 5, lane = tid & 31;
    int wm = wid >> 1, wn = wid & 1;
    int g = lane >> 2, tg = lane & 3;

    int n0g  = blockIdx.x * 64;
    int pos0 = blockIdx.y * 128;

    uint32_t As0 = smem_u32(As);
    uint32_t Bs0 = smem_u32(Bs);
    uint32_t a_off = ((wm * 32 + (lane & 15)) * SRW2 + ((lane >> 4) << 3)) * 2;
    uint32_t b_off = (((wn * 32) + (lane & 7) + ((lane >> 4) << 3)) * SRW2 + (((lane >> 3) & 1) << 3)) * 2;

    float acc[2][4][4];
#pragma unroll
    for (int mt = 0; mt < 2; mt++)
#pragma unroll
        for (int nt = 0; nt < 4; nt++)
#pragma unroll
            for (int i = 0; i < 4; i++) acc[mt][nt][i] = 0.f;

    auto load_stage = [&](int s, int c) {
        int j = c / 5;
        int k0 = (c - j * 5) * 64;
        const __nv_bfloat16* Ag = g_dembh + (size_t)(pos0 + 1 + j) * KP + k0;
        const __nv_bfloat16* Bg = g_Wb + ((size_t)j * NP2 + n0g) * KP + k0;
        uint32_t a_s = As0 + s * A_STG2;
        uint32_t b_s = Bs0 + s * B_STG2;
#pragma unroll
        for (int u = 0; u < 4; u++) {
            int v = tid + u * 256;
            int r = v >> 3, cc = v & 7;
            cpasync16(a_s + (r * SRW2 + cc * 8) * 2, Ag + (size_t)r * KP + cc * 8);
        }
#pragma unroll
        for (int u = 0; u < 2; u++) {
            int v = tid + u * 256;
            int r = v >> 3, cc = v & 7;
            cpasync16(b_s + (r * SRW2 + cc * 8) * 2, Bg + (size_t)r * KP + cc * 8);
        }
        cpasync_commit();
    };

    load_stage(0, 0);

    for (int c = 0; c < 15; c++) {
        int s = c & 1;
        cpasync_wait<0>();
        __syncthreads();
        if (c + 1 < 15) load_stage(s ^ 1, c + 1);

        uint32_t a_base = As0 + s * A_STG2 + a_off;
        uint32_t b_base = Bs0 + s * B_STG2 + b_off;
#pragma unroll
        for (int ks = 0; ks < 4; ks++) {
            uint32_t a[2][4], b[2][4];
            ldsm_x4(a[0], a_base + ks * 32);
            ldsm_x4(a[1], a_base + ks * 32 + 16 * SRW2 * 2);
            ldsm_x4(b[0], b_base + ks * 32);
            ldsm_x4(b[1], b_base + ks * 32 + 16 * SRW2 * 2);
#pragma unroll
            for (int p = 0; p < 2; p++) {
#pragma unroll
                for (int mt = 0; mt < 2; mt++) {
                    mma16816(acc[mt][2 * p + 0], a[mt], b[p][0], b[p][1]);
                    mma16816(acc[mt][2 * p + 1], a[mt], b[p][2], b[p][3]);
                }
            }
        }
    }

#pragma unroll
    for (int mt = 0; mt < 2; mt++) {
#pragma unroll
        for (int nt = 0; nt < 4; nt++) {
            int ch = n0g + wn * 32 + nt * 8 + tg * 2;
            if (ch >= 300) continue;
            float bia0 = __ldg(conv_b + ch);
            float bia1 = __ldg(conv_b + ch + 1);
#pragma unroll
            for (int h = 0; h < 2; h++) {
                int row = pos0 + wm * 32 + mt * 16 + g + h * 8;
                size_t gi = (size_t)row * KP + ch;
                float2 res = __bfloat1622float2(*(const __nv_bfloat162*)&g_dembh[gi]);
                float o0 = fast_sigmoid(acc[mt][nt][h * 2 + 0] + bia0) + res.x;
                float o1 = fast_sigmoid(acc[mt][nt][h * 2 + 1] + bia1) + res.y;
                *(__nv_bfloat162*)&g_dconvh[gi] = __floats2bfloat162_rn(o0, o1);
            }
        }
    }
}

// ---------------- K5: cosine sims as HMMA GEMM, norms inline (3-stage, ldmatrix) ----------------
// grid (D/128, 2 types), 256 threads, 8 warps (warp = 16 d rows). DRAM-bound at ~27us.
#define A_STAGE_SB (128 * SROW * 2)
#define BS_STAGE_B (32 * SROW * 2)
__global__ void __launch_bounds__(256) sim_gemm_kernel() {
    __shared__ __nv_bfloat16 As[3][128][SROW];
    __shared__ __nv_bfloat16 Bs[3][32][SROW];

    int tid = threadIdx.x;
    int wid = tid >> 5, lane = tid & 31;
    int g = lane >> 2, tg = lane & 3;
    int type = blockIdx.y;
    int pos0 = blockIdx.x * 128;

    const __nv_bfloat16* Asrc = type ? g_dconvh : g_dembh;
    const __nv_bfloat16* Bsrc = g_qnh + (size_t)type * Q * KP;

    uint32_t As0 = smem_u32(&As[0][0][0]);
    uint32_t Bs0 = smem_u32(&Bs[0][0][0]);
    uint32_t a_off = ((wid * 16 + (lane & 15)) * SROW + ((lane >> 4) << 3)) * 2;
    uint32_t b_off = (((lane & 7) + ((lane >> 4) << 3)) * SROW + (((lane >> 3) & 1) << 3)) * 2;

    float acc[4][4];
#pragma unroll
    for (int nt = 0; nt < 4; nt++)
#pragma unroll
        for (int i = 0; i < 4; i++) acc[nt][i] = 0.f;
    float ssq0 = 0.f, ssq1 = 0.f;

    auto load_stage = [&](int s, int kc) {
        int k0 = kc * 32;
        const __nv_bfloat16* Ag = Asrc + (size_t)pos0 * KP + k0;
#pragma unroll
        for (int u = 0; u < 2; u++) {
            int v = tid + u * 256;
            int r = v >> 2, cc = v & 3;
            cpasync16(smem_u32(&As[s][r][cc * 8]), Ag + (size_t)r * KP + cc * 8);
        }
        if (tid < 128) {
            int r = tid >> 2, cc = tid & 3;
            cpasync16(smem_u32(&Bs[s][r][cc * 8]), Bsrc + (size_t)r * KP + k0 + cc * 8);
        }
        cpasync_commit();
    };

    load_stage(0, 0);
    load_stage(1, 1);

    for (int kc = 0; kc < 10; kc++) {
        int s = kc % 3;
        if (kc < 9) cpasync_wait<1>();
        else        cpasync_wait<0>();
        __syncthreads();

        uint32_t a_base = As0 + s * A_STAGE_SB + a_off;
        uint32_t b_base = Bs0 + s * BS_STAGE_B + b_off;
#pragma unroll
        for (int ks = 0; ks < 2; ks++) {
            uint32_t a[4], b[2][4];
            ldsm_x4(a, a_base + ks * 32);
            ldsm_x4(b[0], b_base + ks * 32);
            ldsm_x4(b[1], b_base + ks * 32 + 16 * SROW * 2);
            float2 f0 = __bfloat1622float2(*(const __nv_bfloat162*)&a[0]);
            float2 f1 = __bfloat1622float2(*(const __nv_bfloat162*)&a[1]);
            float2 f2 = __bfloat1622float2(*(const __nv_bfloat162*)&a[2]);
            float2 f3 = __bfloat1622float2(*(const __nv_bfloat162*)&a[3]);
            ssq0 = fmaf(f0.x, f0.x, fmaf(f0.y, f0.y, fmaf(f2.x, f2.x, fmaf(f2.y, f2.y, ssq0))));
            ssq1 = fmaf(f1.x, f1.x, fmaf(f1.y, f1.y, fmaf(f3.x, f3.x, fmaf(f3.y, f3.y, ssq1))));
#pragma unroll
            for (int p = 0; p < 2; p++) {
                mma16816(acc[2 * p + 0], a, b[p][0], b[p][1]);
                mma16816(acc[2 * p + 1], a, b[p][2], b[p][3]);
            }
        }
        if (kc + 2 < 10) load_stage((kc + 2) % 3, kc + 2);
    }

    ssq0 += __shfl_xor_sync(0xffffffffu, ssq0, 1);
    ssq0 += __shfl_xor_sync(0xffffffffu, ssq0, 2);
    ssq1 += __shfl_xor_sync(0xffffffffu, ssq1, 1);
    ssq1 += __shfl_xor_sync(0xffffffffu, ssq1, 2);
    float dinv0 = rsqrtf(ssq0);
    float dinv1 = rsqrtf(ssq1);

    int d0 = pos0 + wid * 16 + g;
#pragma unroll
    for (int nt = 0; nt < 4; nt++) {
        int q0 = nt * 8 + tg * 2;
        g_S[type][(size_t)q0 * D + d0]           = acc[nt][0] * dinv0;
        g_S[type][(size_t)(q0 + 1) * D + d0]     = acc[nt][1] * dinv0;
        g_S[type][(size_t)q0 * D + d0 + 8]       = acc[nt][2] * dinv1;
        g_S[type][(size_t)(q0 + 1) * D + d0 + 8] = acc[nt][3] * dinv1;
    }
}

// ---------------- K6: two-stage top-5 ----------------
__device__ __forceinline__ void ins5(float* a, float v) {
    if (v <= a[4]) return;
    a[4] = v;
#pragma unroll
    for (int i = 4; i > 0; i--) {
        if (a[i] > a[i - 1]) { float t = a[i - 1]; a[i - 1] = a[i]; a[i] = t; }
        else break;
    }
}
__device__ __forceinline__ void merge5_xor(float* t5, int off) {
    float o[5];
#pragma unroll
    for (int i = 0; i < 5; i++) o[i] = __shfl_xor_sync(0xffffffffu, t5[i], off);
#pragma unroll
    for (int i = 0; i < 5; i++) ins5(t5, o[i]);
}

__global__ void __launch_bounds__(256) topk1_kernel() {
    int type = blockIdx.x, chunk = blockIdx.y;
    int wid = threadIdx.x >> 5, lane = threadIdx.x & 31;
    const float* src = (type == 0) ? g_ohT : g_S[type - 1];
    for (int qq = 0; qq < 4; qq++) {
        int q = wid * 4 + qq;
        const float4* base = (const float4*)(src + (size_t)q * D + chunk * 2048);
        float t5[5] = {-1e30f, -1e30f, -1e30f, -1e30f, -1e30f};
#pragma unroll 4
        for (int it = 0; it < 16; it++) {
            float4 v = __ldg(base + it * 32 + lane);
            ins5(t5, v.x); ins5(t5, v.y); ins5(t5, v.z); ins5(t5, v.w);
        }
        merge5_xor(t5, 16); merge5_xor(t5, 8); merge5_xor(t5, 4);
        merge5_xor(t5, 2);  merge5_xor(t5, 1);
        if (lane == 0) {
#pragma unroll
            for (int i = 0; i < 5; i++) g_part[type][q][chunk][i] = t5[i];
        }
    }
}

__global__ void __launch_bounds__(1024) topk2_kernel() {
    int type = blockIdx.x;
    int q = threadIdx.x >> 5, lane = threadIdx.x & 31;
    float t5[5] = {-1e30f, -1e30f, -1e30f, -1e30f, -1e30f};
    const float* p = g_part[type][q][lane];
#pragma unroll
    for (int i = 0; i < 5; i++) ins5(t5, p[i]);
    merge5_xor(t5, 16); merge5_xor(t5, 8); merge5_xor(t5, 4);
    merge5_xor(t5, 2);  merge5_xor(t5, 1);
    if (lane == 0) {
        float m = (t5[0] + t5[1] + t5[2] + t5[3] + t5[4]) * 0.2f;
        g_feats[q * 6 + type * 2 + 0] = t5[0];
        g_feats[q * 6 + type * 2 + 1] = m;
    }
}

// ---------------- K7: MLP + emit + loss ----------------
__global__ void final_kernel(const float* __restrict__ W1, const float* __restrict__ b1,
                             const float* __restrict__ W2, const float* __restrict__ b2,
                             const float* __restrict__ a1, const float* __restrict__ target,
                             float* __restrict__ out, int out_size) {
    int q = threadIdx.x;
    float f[6];
#pragma unroll
    for (int j = 0; j < 6; j++) f[j] = g_feats[q * 6 + j];
    float a = a1[0];
    float logit = b2[0];
#pragma unroll
    for (int i = 0; i < 8; i++) {
        float h = b1[i];
#pragma unroll
        for (int j = 0; j < 6; j++) h = fmaf(f[j], W1[i * 6 + j], h);
        h = h > 0.f ? h : a * h;
        logit = fmaf(h, W2[i], logit);
    }
    float s = 1.f / (1.f + expf(-logit));
#pragma unroll
    for (int o = 16; o; o >>= 1) s += __shfl_xor_sync(0xffffffffu, s, o);
    if (q == 0) {
        float emit = s / 32.f;
        float t = target[0];
        float sp = log1pf(expf(-fabsf(emit))) + fmaxf(emit, 0.f);
        float loss = sp - t * emit;
        out[0] = loss;
        if (out_size > 1) out[1] = emit;
    }
}

// ---------------- launch ----------------
extern "C" void kernel_launch(void* const* d_in, const int* in_sizes, int n_in,
                              void* d_out, int out_size) {
    const int*   doc1     = (const int*)d_in[0];
    const int*   question = (const int*)d_in[1];
    const float* doc1_sim = (const float*)d_in[2];
    const float* target   = (const float*)d_in[3];
    const float* embeds   = (const float*)d_in[4];
    const float* conv_w   = (const float*)d_in[5];
    const float* conv_b   = (const float*)d_in[6];
    const float* W1       = (const float*)d_in[7];
    const float* b1       = (const float*)d_in[8];
    const float* W2       = (const float*)d_in[9];
    const float* b2       = (const float*)d_in[10];
    const float* a1       = (const float*)d_in[11];
    float* out = (float*)d_out;

    cudaFuncSetAttribute(conv_gemm_kernel,
                         cudaFuncAttributeMaxDynamicSharedMemorySize, CONV_SMEM);

    wb_kernel<<<(3 * NP2 * KP + 255) / 256, 256>>>(conv_w);             // 1
    conv_q_kernel<<<Q, 384>>>(question, embeds, conv_w, conv_b);         // 2
    gather_kernel<<<D / 8, 256>>>(doc1, embeds);                         // 3
    {
        dim3 grid(5, D / 128);
        conv_gemm_kernel<<<grid, 256, CONV_SMEM>>>(conv_b);              // 4: ncu capture target
    }
    transpose_kernel<<<D / 32, 256>>>(doc1_sim);                         // 5
    {
        dim3 grid(D / 128, 2);
        sim_gemm_kernel<<<grid, 256>>>();                                // 6
    }
    {
        dim3 grid(3, 32);
        topk1_kernel<<<grid, 256>>>();                                   // 7
    }
    topk2_kernel<<<3, 1024>>>();                                         // 8
    final_kernel<<<1, 32>>>(W1, b1, W2, b2, a1, target, out, out_size);  // 9
}

// round 17
// speedup vs baseline: 1.1749x; 1.0155x over previous
#include <cuda_runtime.h>
#include <cuda_bf16.h>
#include <math.h>
#include <stdint.h>

#define D    65536
#define Q    32
#define E    300
#define KP   320          // padded k (input channels)
#define NP2  320          // padded n (output channels)
#define SROW 40           // smem row pitch (bf16) for sim kernel (k-chunk 32)
#define SRW2 72           // smem row pitch (bf16) for conv kernel (k-chunk 64)

// ---------------- device scratch (static, allowed) ----------------
__device__ __nv_bfloat16 g_Wb[3 * NP2 * KP];               // bf16 weights [j][e][i], zero-padded
__device__ __nv_bfloat16 g_dembh[(size_t)(D + 16) * KP];   // bf16 doc embeds (pads stay zero)
__device__ __nv_bfloat16 g_dconvh[(size_t)(D + 16) * KP];  // bf16 doc conv+residual (pads zero)
__device__ __nv_bfloat16 g_qnh[2 * Q * KP];                // bf16 normalized q vecs (emb, conv)
__device__ float g_ohT[(size_t)Q * D];                     // transposed doc1_sim [q][d]
__device__ float g_S[2][(size_t)Q * D];                    // sims [q][d]: 0 emb, 1 conv
__device__ float g_part[3][Q][32][5];                      // stage-1 top5 partials
__device__ float g_feats[Q * 6];

// ---------------- PTX helpers ----------------
__device__ __forceinline__ uint32_t smem_u32(const void* p) {
    uint32_t a;
    asm("{ .reg .u64 t; cvta.to.shared.u64 t, %1; cvt.u32.u64 %0, t; }" : "=r"(a) : "l"(p));
    return a;
}
__device__ __forceinline__ void cpasync16(uint32_t s, const void* g) {
    asm volatile("cp.async.cg.shared.global [%0], [%1], 16;" :: "r"(s), "l"(g));
}
__device__ __forceinline__ void cpasync_commit() {
    asm volatile("cp.async.commit_group;" ::: "memory");
}
template <int N>
__device__ __forceinline__ void cpasync_wait() {
    asm volatile("cp.async.wait_group %0;" :: "n"(N) : "memory");
}
__device__ __forceinline__ void mma16816(float* c, const uint32_t* a, uint32_t b0, uint32_t b1) {
    asm volatile(
        "mma.sync.aligned.m16n8k16.row.col.f32.bf16.bf16.f32 "
        "{%0,%1,%2,%3}, {%4,%5,%6,%7}, {%8,%9}, {%0,%1,%2,%3};"
        : "+f"(c[0]), "+f"(c[1]), "+f"(c[2]), "+f"(c[3])
        : "r"(a[0]), "r"(a[1]), "r"(a[2]), "r"(a[3]), "r"(b0), "r"(b1));
}
__device__ __forceinline__ void ldsm_x4(uint32_t* r, uint32_t addr) {
    asm volatile("ldmatrix.sync.aligned.m8n8.x4.shared.b16 {%0,%1,%2,%3}, [%4];"
                 : "=r"(r[0]), "=r"(r[1]), "=r"(r[2]), "=r"(r[3]) : "r"(addr));
}
__device__ __forceinline__ float fast_sigmoid(float x) {
    return 1.f / (1.f + __expf(-x));
}

// ---------------- K0: bf16 GEMM weights [j][e][i], padded ----------------
__global__ void wb_kernel(const float* __restrict__ conv_w) {
    int idx = blockIdx.x * 256 + threadIdx.x;
    if (idx >= 3 * NP2 * KP) return;
    int i = idx % KP;
    int rem = idx / KP;
    int e = rem % NP2;
    int j = rem / NP2;
    float v = (i < 300 && e < 300) ? conv_w[e * 900 + i * 3 + j] : 0.f;
    g_Wb[idx] = __float2bfloat16(v);
}

// ---------------- K1: doc gather -> bf16 padded (warp per row, vectorized) ----------------
__global__ void gather_kernel(const int* __restrict__ doc1, const float* __restrict__ embeds) {
    int row = blockIdx.x * 8 + (threadIdx.x >> 5);
    int lane = threadIdx.x & 31;
    if (row >= D) return;
    const float4* src = (const float4*)(embeds + (size_t)doc1[row] * 300);
    __nv_bfloat16* dst = g_dembh + (size_t)row * KP;
    for (int i = lane; i < 75; i += 32) {
        float4 v = src[i];
        __nv_bfloat162 lo = __floats2bfloat162_rn(v.x, v.y);
        __nv_bfloat162 hi = __floats2bfloat162_rn(v.z, v.w);
        uint2 pk;
        pk.x = *(uint32_t*)&lo;
        pk.y = *(uint32_t*)&hi;
        *(uint2*)(dst + i * 4) = pk;
    }
}

// ---------------- K2: query conv + normalize -> bf16 (parallel) ----------------
__global__ void __launch_bounds__(384) conv_q_kernel(const int* __restrict__ question,
                                                     const float* __restrict__ embeds,
                                                     const float* __restrict__ conv_w,
                                                     const float* __restrict__ conv_b) {
    __shared__ float xs4[4][300];
    __shared__ float qc[300];
    __shared__ float red[2];
    int t = blockIdx.x;
    int tid = threadIdx.x;
    int wid = tid >> 5, lane = tid & 31;

    for (int idx = tid; idx < 1200; idx += 384) {
        int j = idx / 300, i = idx - j * 300;
        int tt = t + j;
        xs4[j][i] = (tt < Q) ? embeds[(size_t)question[tt] * 300 + i] : 0.f;
    }
    __syncthreads();

    for (int e = wid; e < 300; e += 12) {
        const float* w = conv_w + e * 900;
        float acc = 0.f;
        for (int kk = lane; kk < 900; kk += 32) {
            int i = kk / 3, j = kk - 3 * i;
            acc = fmaf(w[kk], xs4[1 + j][i], acc);
        }
#pragma unroll
        for (int o = 16; o; o >>= 1) acc += __shfl_down_sync(0xffffffffu, acc, o);
        if (lane == 0)
            qc[e] = fast_sigmoid(acc + conv_b[e]) + xs4[0][e];
    }
    __syncthreads();
    if (wid == 0) {
        float se = 0.f, sc = 0.f;
        for (int i = lane; i < 300; i += 32) {
            float a = xs4[0][i]; se += a * a;
            float c = qc[i];     sc += c * c;
        }
#pragma unroll
        for (int o = 16; o; o >>= 1) {
            se += __shfl_xor_sync(0xffffffffu, se, o);
            sc += __shfl_xor_sync(0xffffffffu, sc, o);
        }
        if (lane == 0) { red[0] = rsqrtf(se); red[1] = rsqrtf(sc); }
    }
    __syncthreads();
    if (tid < 300) {
        g_qnh[0 * Q * KP + t * KP + tid] = __float2bfloat16(xs4[0][tid] * red[0]);
        g_qnh[1 * Q * KP + t * KP + tid] = __float2bfloat16(qc[tid] * red[1]);
    }
}

// ---------------- K3: transpose doc1_sim [D][Q] -> g_ohT [Q][D] ----------------
__global__ void __launch_bounds__(256) transpose_kernel(const float* __restrict__ doc1_sim) {
    __shared__ float tbuf[32][33];
    int d0 = blockIdx.x * 32;
    int tx = threadIdx.x & 31, ty = threadIdx.x >> 5;
    for (int r = ty; r < 32; r += 8)
        tbuf[r][tx] = doc1_sim[(size_t)(d0 + r) * 32 + tx];
    __syncthreads();
    for (int r = ty; r < 32; r += 8)
        g_ohT[(size_t)r * D + d0 + tx] = tbuf[tx][r];
}

// ---------------- K4: doc conv as HMMA bf16 GEMM — shared-A 3-tap version ----------------
// grid (5, 512): x = 64-channel tile, y = 128-doc tile. 256 threads (8 warps, 4m x 2n, warp 32x32).
// One 136-row A tile per 64-wide k-chunk serves all 3 conv taps (row shift = +j in smem).
// 5 chunks total, 2 buffers, 1 sync per chunk. Stage = A 136x72 + B 3x64x72 (bf16) = 47232 B.
#define A_ROWS3 136
#define A_STG3 (A_ROWS3 * SRW2 * 2)       // 19584 B
#define B_STG3 (3 * 64 * SRW2 * 2)        // 27648 B
#define CONV_SMEM (2 * (A_STG3 + B_STG3)) // 94464 B
__global__ void __launch_bounds__(256, 2) conv_gemm_kernel(const float* __restrict__ conv_b) {
    extern __shared__ __nv_bfloat16 dyn_smem[];
    __nv_bfloat16* As = dyn_smem;                          // [2][136][SRW2]
    __nv_bfloat16* Bs = dyn_smem + 2 * A_ROWS3 * SRW2;     // [2][3][64][SRW2]

    int tid = threadIdx.x;
    int wid = tid >> 5, lane = tid & 31;
    int wm = wid >> 1, wn = wid & 1;
    int g = lane >> 2, tg = lane & 3;

    int n0g  = blockIdx.x * 64;
    int pos0 = blockIdx.y * 128;

    uint32_t As0 = smem_u32(As);
    uint32_t Bs0 = smem_u32(Bs);
    // tap-0 fragment rows start at smem row 1 (= doc row pos0+1); tap j adds j*SRW2*2.
    uint32_t a_off = ((wm * 32 + (lane & 15) + 1) * SRW2 + ((lane >> 4) << 3)) * 2;
    uint32_t b_off = (((wn * 32) + (lane & 7) + ((lane >> 4) << 3)) * SRW2 + (((lane >> 3) & 1) << 3)) * 2;

    float acc[2][4][4];
#pragma unroll
    for (int mt = 0; mt < 2; mt++)
#pragma unroll
        for (int nt = 0; nt < 4; nt++)
#pragma unroll
            for (int i = 0; i < 4; i++) acc[mt][nt][i] = 0.f;

    // chunk c: k0 = c*64; A rows [pos0, pos0+136); B = 3 tap tiles of 64 rows
    auto load_stage = [&](int s, int c) {
        int k0 = c * 64;
        const __nv_bfloat16* Ag = g_dembh + (size_t)pos0 * KP + k0;
        uint32_t a_s = As0 + s * A_STG3;
        uint32_t b_s = Bs0 + s * B_STG3;
#pragma unroll
        for (int u = 0; u < 5; u++) {
            int v = tid + u * 256;              // 1088 tasks: 136 rows x 8 chunks of 16B
            if (v < A_ROWS3 * 8) {
                int r = v >> 3, cc = v & 7;
                cpasync16(a_s + (r * SRW2 + cc * 8) * 2, Ag + (size_t)r * KP + cc * 8);
            }
        }
#pragma unroll
        for (int u = 0; u < 6; u++) {
            int v = tid + u * 256;              // 1536 tasks: 3 taps x 64 rows x 8 chunks
            int j = v / 512;
            int rr = (v - j * 512) >> 3, cc = v & 7;
            const __nv_bfloat16* Bg = g_Wb + ((size_t)j * NP2 + n0g) * KP + k0;
            cpasync16(b_s + ((j * 64 + rr) * SRW2 + cc * 8) * 2, Bg + (size_t)rr * KP + cc * 8);
        }
        cpasync_commit();
    };

    load_stage(0, 0);

    for (int c = 0; c < 5; c++) {
        int s = c & 1;
        cpasync_wait<0>();
        __syncthreads();
        if (c + 1 < 5) load_stage(s ^ 1, c + 1);

        uint32_t a_base = As0 + s * A_STG3 + a_off;
        uint32_t b_base = Bs0 + s * B_STG3 + b_off;
#pragma unroll
        for (int j = 0; j < 3; j++) {
            uint32_t ab = a_base + j * (SRW2 * 2);
            uint32_t bb = b_base + j * (64 * SRW2 * 2);
#pragma unroll
            for (int ks = 0; ks < 4; ks++) {
                uint32_t a[2][4], b[2][4];
                ldsm_x4(a[0], ab + ks * 32);
                ldsm_x4(a[1], ab + ks * 32 + 16 * SRW2 * 2);
                ldsm_x4(b[0], bb + ks * 32);
                ldsm_x4(b[1], bb + ks * 32 + 16 * SRW2 * 2);
#pragma unroll
                for (int p = 0; p < 2; p++) {
#pragma unroll
                    for (int mt = 0; mt < 2; mt++) {
                        mma16816(acc[mt][2 * p + 0], a[mt], b[p][0], b[p][1]);
                        mma16816(acc[mt][2 * p + 1], a[mt], b[p][2], b[p][3]);
                    }
                }
            }
        }
    }

    // epilogue: +bias, sigmoid, +residual(bf16), store bf16x2
#pragma unroll
    for (int mt = 0; mt < 2; mt++) {
#pragma unroll
        for (int nt = 0; nt < 4; nt++) {
            int ch = n0g + wn * 32 + nt * 8 + tg * 2;
            if (ch >= 300) continue;
            float bia0 = __ldg(conv_b + ch);
            float bia1 = __ldg(conv_b + ch + 1);
#pragma unroll
            for (int h = 0; h < 2; h++) {
                int row = pos0 + wm * 32 + mt * 16 + g + h * 8;
                size_t gi = (size_t)row * KP + ch;
                float2 res = __bfloat1622float2(*(const __nv_bfloat162*)&g_dembh[gi]);
                float o0 = fast_sigmoid(acc[mt][nt][h * 2 + 0] + bia0) + res.x;
                float o1 = fast_sigmoid(acc[mt][nt][h * 2 + 1] + bia1) + res.y;
                *(__nv_bfloat162*)&g_dconvh[gi] = __floats2bfloat162_rn(o0, o1);
            }
        }
    }
}

// ---------------- K5: cosine sims as HMMA GEMM, norms inline (3-stage, ldmatrix) ----------------
#define A_STAGE_SB (128 * SROW * 2)
#define BS_STAGE_B (32 * SROW * 2)
__global__ void __launch_bounds__(256) sim_gemm_kernel() {
    __shared__ __nv_bfloat16 As[3][128][SROW];
    __shared__ __nv_bfloat16 Bs[3][32][SROW];

    int tid = threadIdx.x;
    int wid = tid >> 5, lane = tid & 31;
    int g = lane >> 2, tg = lane & 3;
    int type = blockIdx.y;
    int pos0 = blockIdx.x * 128;

    const __nv_bfloat16* Asrc = type ? g_dconvh : g_dembh;
    const __nv_bfloat16* Bsrc = g_qnh + (size_t)type * Q * KP;

    uint32_t As0 = smem_u32(&As[0][0][0]);
    uint32_t Bs0 = smem_u32(&Bs[0][0][0]);
    uint32_t a_off = ((wid * 16 + (lane & 15)) * SROW + ((lane >> 4) << 3)) * 2;
    uint32_t b_off = (((lane & 7) + ((lane >> 4) << 3)) * SROW + (((lane >> 3) & 1) << 3)) * 2;

    float acc[4][4];
#pragma unroll
    for (int nt = 0; nt < 4; nt++)
#pragma unroll
        for (int i = 0; i < 4; i++) acc[nt][i] = 0.f;
    float ssq0 = 0.f, ssq1 = 0.f;

    auto load_stage = [&](int s, int kc) {
        int k0 = kc * 32;
        const __nv_bfloat16* Ag = Asrc + (size_t)pos0 * KP + k0;
#pragma unroll
        for (int u = 0; u < 2; u++) {
            int v = tid + u * 256;
            int r = v >> 2, cc = v & 3;
            cpasync16(smem_u32(&As[s][r][cc * 8]), Ag + (size_t)r * KP + cc * 8);
        }
        if (tid < 128) {
            int r = tid >> 2, cc = tid & 3;
            cpasync16(smem_u32(&Bs[s][r][cc * 8]), Bsrc + (size_t)r * KP + k0 + cc * 8);
        }
        cpasync_commit();
    };

    load_stage(0, 0);
    load_stage(1, 1);

    for (int kc = 0; kc < 10; kc++) {
        int s = kc % 3;
        if (kc < 9) cpasync_wait<1>();
        else        cpasync_wait<0>();
        __syncthreads();

        uint32_t a_base = As0 + s * A_STAGE_SB + a_off;
        uint32_t b_base = Bs0 + s * BS_STAGE_B + b_off;
#pragma unroll
        for (int ks = 0; ks < 2; ks++) {
            uint32_t a[4], b[2][4];
            ldsm_x4(a, a_base + ks * 32);
            ldsm_x4(b[0], b_base + ks * 32);
            ldsm_x4(b[1], b_base + ks * 32 + 16 * SROW * 2);
            float2 f0 = __bfloat1622float2(*(const __nv_bfloat162*)&a[0]);
            float2 f1 = __bfloat1622float2(*(const __nv_bfloat162*)&a[1]);
            float2 f2 = __bfloat1622float2(*(const __nv_bfloat162*)&a[2]);
            float2 f3 = __bfloat1622float2(*(const __nv_bfloat162*)&a[3]);
            ssq0 = fmaf(f0.x, f0.x, fmaf(f0.y, f0.y, fmaf(f2.x, f2.x, fmaf(f2.y, f2.y, ssq0))));
            ssq1 = fmaf(f1.x, f1.x, fmaf(f1.y, f1.y, fmaf(f3.x, f3.x, fmaf(f3.y, f3.y, ssq1))));
#pragma unroll
            for (int p = 0; p < 2; p++) {
                mma16816(acc[2 * p + 0], a, b[p][0], b[p][1]);
                mma16816(acc[2 * p + 1], a, b[p][2], b[p][3]);
            }
        }
        if (kc + 2 < 10) load_stage((kc + 2) % 3, kc + 2);
    }

    ssq0 += __shfl_xor_sync(0xffffffffu, ssq0, 1);
    ssq0 += __shfl_xor_sync(0xffffffffu, ssq0, 2);
    ssq1 += __shfl_xor_sync(0xffffffffu, ssq1, 1);
    ssq1 += __shfl_xor_sync(0xffffffffu, ssq1, 2);
    float dinv0 = rsqrtf(ssq0);
    float dinv1 = rsqrtf(ssq1);

    int d0 = pos0 + wid * 16 + g;
#pragma unroll
    for (int nt = 0; nt < 4; nt++) {
        int q0 = nt * 8 + tg * 2;
        g_S[type][(size_t)q0 * D + d0]           = acc[nt][0] * dinv0;
        g_S[type][(size_t)(q0 + 1) * D + d0]     = acc[nt][1] * dinv0;
        g_S[type][(size_t)q0 * D + d0 + 8]       = acc[nt][2] * dinv1;
        g_S[type][(size_t)(q0 + 1) * D + d0 + 8] = acc[nt][3] * dinv1;
    }
}

// ---------------- K6: two-stage top-5 ----------------
__device__ __forceinline__ void ins5(float* a, float v) {
    if (v <= a[4]) return;
    a[4] = v;
#pragma unroll
    for (int i = 4; i > 0; i--) {
        if (a[i] > a[i - 1]) { float t = a[i - 1]; a[i - 1] = a[i]; a[i] = t; }
        else break;
    }
}
__device__ __forceinline__ void merge5_xor(float* t5, int off) {
    float o[5];
#pragma unroll
    for (int i = 0; i < 5; i++) o[i] = __shfl_xor_sync(0xffffffffu, t5[i], off);
#pragma unroll
    for (int i = 0; i < 5; i++) ins5(t5, o[i]);
}

__global__ void __launch_bounds__(256) topk1_kernel() {
    int type = blockIdx.x, chunk = blockIdx.y;
    int wid = threadIdx.x >> 5, lane = threadIdx.x & 31;
    const float* src = (type == 0) ? g_ohT : g_S[type - 1];
    for (int qq = 0; qq < 4; qq++) {
        int q = wid * 4 + qq;
        const float4* base = (const float4*)(src + (size_t)q * D + chunk * 2048);
        float t5[5] = {-1e30f, -1e30f, -1e30f, -1e30f, -1e30f};
#pragma unroll 4
        for (int it = 0; it < 16; it++) {
            float4 v = __ldg(base + it * 32 + lane);
            ins5(t5, v.x); ins5(t5, v.y); ins5(t5, v.z); ins5(t5, v.w);
        }
        merge5_xor(t5, 16); merge5_xor(t5, 8); merge5_xor(t5, 4);
        merge5_xor(t5, 2);  merge5_xor(t5, 1);
        if (lane == 0) {
#pragma unroll
            for (int i = 0; i < 5; i++) g_part[type][q][chunk][i] = t5[i];
        }
    }
}

__global__ void __launch_bounds__(1024) topk2_kernel() {
    int type = blockIdx.x;
    int q = threadIdx.x >> 5, lane = threadIdx.x & 31;
    float t5[5] = {-1e30f, -1e30f, -1e30f, -1e30f, -1e30f};
    const float* p = g_part[type][q][lane];
#pragma unroll
    for (int i = 0; i < 5; i++) ins5(t5, p[i]);
    merge5_xor(t5, 16); merge5_xor(t5, 8); merge5_xor(t5, 4);
    merge5_xor(t5, 2);  merge5_xor(t5, 1);
    if (lane == 0) {
        float m = (t5[0] + t5[1] + t5[2] + t5[3] + t5[4]) * 0.2f;
        g_feats[q * 6 + type * 2 + 0] = t5[0];
        g_feats[q * 6 + type * 2 + 1] = m;
    }
}

// ---------------- K7: MLP + emit + loss ----------------
__global__ void final_kernel(const float* __restrict__ W1, const float* __restrict__ b1,
                             const float* __restrict__ W2, const float* __restrict__ b2,
                             const float* __restrict__ a1, const float* __restrict__ target,
                             float* __restrict__ out, int out_size) {
    int q = threadIdx.x;
    float f[6];
#pragma unroll
    for (int j = 0; j < 6; j++) f[j] = g_feats[q * 6 + j];
    float a = a1[0];
    float logit = b2[0];
#pragma unroll
    for (int i = 0; i < 8; i++) {
        float h = b1[i];
#pragma unroll
        for (int j = 0; j < 6; j++) h = fmaf(f[j], W1[i * 6 + j], h);
        h = h > 0.f ? h : a * h;
        logit = fmaf(h, W2[i], logit);
    }
    float s = 1.f / (1.f + expf(-logit));
#pragma unroll
    for (int o = 16; o; o >>= 1) s += __shfl_xor_sync(0xffffffffu, s, o);
    if (q == 0) {
        float emit = s / 32.f;
        float t = target[0];
        float sp = log1pf(expf(-fabsf(emit))) + fmaxf(emit, 0.f);
        float loss = sp - t * emit;
        out[0] = loss;
        if (out_size > 1) out[1] = emit;
    }
}

// ---------------- launch ----------------
extern "C" void kernel_launch(void* const* d_in, const int* in_sizes, int n_in,
                              void* d_out, int out_size) {
    const int*   doc1     = (const int*)d_in[0];
    const int*   question = (const int*)d_in[1];
    const float* doc1_sim = (const float*)d_in[2];
    const float* target   = (const float*)d_in[3];
    const float* embeds   = (const float*)d_in[4];
    const float* conv_w   = (const float*)d_in[5];
    const float* conv_b   = (const float*)d_in[6];
    const float* W1       = (const float*)d_in[7];
    const float* b1       = (const float*)d_in[8];
    const float* W2       = (const float*)d_in[9];
    const float* b2       = (const float*)d_in[10];
    const float* a1       = (const float*)d_in[11];
    float* out = (float*)d_out;

    cudaFuncSetAttribute(conv_gemm_kernel,
                         cudaFuncAttributeMaxDynamicSharedMemorySize, CONV_SMEM);

    wb_kernel<<<(3 * NP2 * KP + 255) / 256, 256>>>(conv_w);             // 1
    conv_q_kernel<<<Q, 384>>>(question, embeds, conv_w, conv_b);         // 2
    gather_kernel<<<D / 8, 256>>>(doc1, embeds);                         // 3
    {
        dim3 grid(5, D / 128);
        conv_gemm_kernel<<<grid, 256, CONV_SMEM>>>(conv_b);              // 4: ncu capture target
    }
    transpose_kernel<<<D / 32, 256>>>(doc1_sim);                         // 5
    {
        dim3 grid(D / 128, 2);
        sim_gemm_kernel<<<grid, 256>>>();                                // 6
    }
    {
        dim3 grid(3, 32);
        topk1_kernel<<<grid, 256>>>();                                   // 7
    }
    topk2_kernel<<<3, 1024>>>();                                         // 8
    final_kernel<<<1, 32>>>(W1, b1, W2, b2, a1, target, out, out_size);  // 9
}